// round 1
// baseline (speedup 1.0000x reference)
#include <cuda_runtime.h>
#include <math.h>

#define BB 16
#define NN 4096
#define CC 256
#define KK 8
#define EPSF 1e-6f
#define RATIOF 0.1f
#define NTOK (BB*NN)          // 65536
#define GATE_BLOCKS (NTOK/8)  // 8192

// ---------------- scratch (no allocs allowed) ----------------
__device__ float          g_geno[BB*KK];
__device__ unsigned short g_route_e[NTOK];   // e0 | e1<<8
__device__ float2         g_route_w[NTOK];   // w0, w1
__device__ float          g_conf[GATE_BLOCKS];
__device__ int            g_usage[KK];
__device__ float          g_hacc[BB*KK*CC];  // sum_n w * relu(tok@W1^T+b1)
__device__ float          g_mass[BB*KK];

// ---------------- geno term + usage reset ----------------
__global__ void geno_kernel(const float* __restrict__ geno_vec,
                            const float* __restrict__ Wgg,
                            const float* __restrict__ bgg) {
    int t = threadIdx.x;            // 128 threads = B*K
    int b = t / KK, k = t % KK;
    const float* g = geno_vec + b * CC;
    const float* w = Wgg + k * CC;
    float s = 0.f;
#pragma unroll 8
    for (int i = 0; i < CC; i++) s += g[i] * w[i];
    g_geno[t] = RATIOF * (s + bgg[k]);
    if (t < KK) g_usage[t] = 0;
}

// ---------------- gate: logits, top-2, softmax ----------------
__global__ void gate_kernel(const float* __restrict__ tokens,
                            const float* __restrict__ Wg,
                            const float* __restrict__ bg) {
    __shared__ float4 sWg[KK * 64];   // [k][64 float4] = 8KB
    __shared__ float  sconf[8];
    int tid = threadIdx.x;
    for (int i = tid; i < KK * 64; i += 256) sWg[i] = ((const float4*)Wg)[i];
    __syncthreads();

    int warp = tid >> 5, lane = tid & 31;
    int t = blockIdx.x * 8 + warp;            // token id (always < NTOK)
    int b = t >> 12;                           // /NN

    const float4* tok4 = (const float4*)(tokens + (size_t)t * CC);
    float acc[KK];
#pragma unroll
    for (int k = 0; k < KK; k++) acc[k] = 0.f;
#pragma unroll
    for (int i = 0; i < 2; i++) {
        float4 tv = tok4[i * 32 + lane];
#pragma unroll
        for (int k = 0; k < KK; k++) {
            float4 w = sWg[k * 64 + i * 32 + lane];
            acc[k] += tv.x * w.x + tv.y * w.y + tv.z * w.z + tv.w * w.w;
        }
    }
#pragma unroll
    for (int k = 0; k < KK; k++) {
#pragma unroll
        for (int off = 16; off; off >>= 1)
            acc[k] += __shfl_xor_sync(0xffffffffu, acc[k], off);
    }
    if (lane == 0) {
        float lg[KK];
#pragma unroll
        for (int k = 0; k < KK; k++) lg[k] = acc[k] + bg[k] + g_geno[b * KK + k];
        // top-2 with lowest-index tie break (matches jax.lax.top_k)
        int i0 = 0; float v0 = lg[0];
#pragma unroll
        for (int k = 1; k < KK; k++) if (lg[k] > v0) { v0 = lg[k]; i0 = k; }
        float v1 = -1e30f; int i1 = 0;
#pragma unroll
        for (int k = 0; k < KK; k++)
            if (k != i0 && lg[k] > v1) { v1 = lg[k]; i1 = k; }
        float e  = expf(v1 - v0);
        float w0 = 1.f / (1.f + e);
        float w1 = e / (1.f + e);
        w0 = fmaxf(w0, EPSF); w1 = fmaxf(w1, EPSF);
        float s = w0 + w1; w0 /= s; w1 /= s;
        g_route_e[t] = (unsigned short)(i0 | (i1 << 8));
        g_route_w[t] = make_float2(w0, w1);
        atomicAdd(&g_usage[i0], 1);
        atomicAdd(&g_usage[i1], 1);
        sconf[warp] = v0 - v1;
    }
    __syncthreads();
    if (tid == 0) {
        float cs = 0.f;
#pragma unroll
        for (int w = 0; w < 8; w++) cs += sconf[w];
        g_conf[blockIdx.x] = cs;
    }
}

// ---------------- expert layer-1 + weighted token reduce ----------------
// 128 blocks = (b,k). 1024 threads: warp = (rg in 0..3, q in 0..7),
// thread holds W1[k][row][q*32 .. q*32+31] in 32 registers (2 row passes of 128).
__global__ void __launch_bounds__(1024, 1)
expert_kernel(const float* __restrict__ tokens,
              const float* __restrict__ W1,
              const float* __restrict__ b1) {
    __shared__ float4 stok[2][64];             // double-buffered token
    __shared__ float  spart[8][128];           // q-partials per row
    __shared__ unsigned short slist[NN];
    __shared__ float  swt[NN];
    __shared__ int    scnt;

    int bk = blockIdx.x;
    int b = bk >> 3, k = bk & 7;
    int tid = threadIdx.x;
    int warp = tid >> 5, lane = tid & 31;
    int q = warp & 7, rg = warp >> 3;

    // deterministic compaction (n-order) of tokens routed to expert k
    if (warp == 0) {
        int cnt = 0;
        for (int base = 0; base < NN; base += 32) {
            int n = base + lane;
            unsigned short e = g_route_e[b * NN + n];
            float2 wv = g_route_w[b * NN + n];
            bool m0 = (e & 0xff) == k;
            bool m1 = (e >> 8)   == k;
            bool hit = m0 || m1;
            unsigned bal = __ballot_sync(0xffffffffu, hit);
            if (hit) {
                int pos = cnt + __popc(bal & ((1u << lane) - 1u));
                slist[pos] = (unsigned short)n;
                swt[pos]   = m0 ? wv.x : wv.y;
            }
            cnt += __popc(bal);
        }
        if (lane == 0) scnt = cnt;
    }
    __syncthreads();
    int cnt = scnt;

    if (warp == 0) {                  // mass (fixed strided order: deterministic)
        float ms = 0.f;
        for (int i = lane; i < cnt; i += 32) ms += swt[i];
#pragma unroll
        for (int off = 16; off; off >>= 1) ms += __shfl_xor_sync(0xffffffffu, ms, off);
        if (lane == 0) g_mass[bk] = ms;
    }

    const float* W1k = W1 + (size_t)k * CC * CC;

    for (int pass = 0; pass < 2; pass++) {
        int rowg = pass * 128 + rg * 32 + lane;
        float4 w1r[8];
        const float4* wrow = (const float4*)(W1k + (size_t)rowg * CC + q * 32);
#pragma unroll
        for (int m = 0; m < 8; m++) w1r[m] = wrow[m];

        float b1r = 0.f, accv = 0.f;
        if (tid < 128) b1r = b1[k * CC + pass * 128 + tid];

        if (cnt > 0 && tid < 64) {    // preload token 0
            const float4* src = (const float4*)(tokens + ((size_t)b * NN + slist[0]) * CC);
            stok[0][tid] = src[tid];
        }
        __syncthreads();

        for (int it = 0; it < cnt; it++) {
            int cur = it & 1;
            float4 pf;
            bool dopf = (tid < 64) && (it + 1 < cnt);
            if (dopf) {
                const float4* src = (const float4*)(tokens + ((size_t)b * NN + slist[it + 1]) * CC);
                pf = src[tid];
            }
            float part = 0.f;
#pragma unroll
            for (int m = 0; m < 8; m++) {
                float4 tv = stok[cur][q * 8 + m];
                part += w1r[m].x * tv.x + w1r[m].y * tv.y
                      + w1r[m].z * tv.z + w1r[m].w * tv.w;
            }
            spart[q][rg * 32 + lane] = part;
            if (dopf) stok[1 - cur][tid] = pf;
            __syncthreads();
            if (tid < 128) {
                float sum = spart[0][tid] + spart[1][tid] + spart[2][tid] + spart[3][tid]
                          + spart[4][tid] + spart[5][tid] + spart[6][tid] + spart[7][tid];
                float y = fmaxf(sum + b1r, 0.f);
                accv += swt[it] * y;
            }
            __syncthreads();
        }
        if (tid < 128) g_hacc[bk * CC + pass * 128 + tid] = accv;
        __syncthreads();
    }
}

// ---------------- layer-2 + normalize -> centers ----------------
__global__ void out_kernel(const float* __restrict__ W2,
                           const float* __restrict__ b2,
                           float* __restrict__ out) {
    __shared__ float sh[CC];
    int bk = blockIdx.x;
    int k = bk & 7;
    int c = threadIdx.x;
    sh[c] = g_hacc[bk * CC + c];
    __syncthreads();
    const float4* w4 = (const float4*)(W2 + ((size_t)k * CC + c) * CC);
    float s = 0.f;
#pragma unroll 8
    for (int j = 0; j < CC / 4; j++) {
        float4 w = w4[j];
        s += sh[4*j] * w.x + sh[4*j+1] * w.y + sh[4*j+2] * w.z + sh[4*j+3] * w.w;
    }
    float mass = g_mass[bk];
    s += mass * b2[k * CC + c];
    s /= fmaxf(mass, EPSF);
    out[bk * CC + c] = s;
}

// ---------------- scalars: lb_loss + routing_confidence ----------------
__global__ void fin_kernel(float* __restrict__ out) {
    __shared__ float sred[256];
    int tid = threadIdx.x;
    float s = 0.f;
    for (int i = tid; i < GATE_BLOCKS; i += 256) s += g_conf[i];
    sred[tid] = s;
    __syncthreads();
    for (int off = 128; off; off >>= 1) {
        if (tid < off) sred[tid] += sred[tid + off];
        __syncthreads();
    }
    if (tid == 0) {
        float rc = sred[0] / (float)NTOK;
        float u[KK]; float mean = 0.f;
#pragma unroll
        for (int k = 0; k < KK; k++) { u[k] = (float)g_usage[k] / (float)NTOK; mean += u[k]; }
        mean /= (float)KK;
        float var = 0.f;
#pragma unroll
        for (int k = 0; k < KK; k++) { float d = u[k] - mean; var += d * d; }
        var /= (float)KK;
        float den = mean + EPSF;
        out[BB * KK * CC]     = var / (den * den);   // (std/(mean+eps))^2
        out[BB * KK * CC + 1] = rc;
    }
}

// ---------------- launch ----------------
extern "C" void kernel_launch(void* const* d_in, const int* in_sizes, int n_in,
                              void* d_out, int out_size) {
    const float* tokens = (const float*)d_in[0];
    const float* geno   = (const float*)d_in[1];
    const float* Wg     = (const float*)d_in[2];
    const float* bg     = (const float*)d_in[3];
    const float* Wgg    = (const float*)d_in[4];
    const float* bgg    = (const float*)d_in[5];
    const float* W1     = (const float*)d_in[6];
    const float* b1     = (const float*)d_in[7];
    const float* W2     = (const float*)d_in[8];
    const float* b2     = (const float*)d_in[9];
    float* out = (float*)d_out;

    geno_kernel<<<1, 128>>>(geno, Wgg, bgg);
    gate_kernel<<<GATE_BLOCKS, 256>>>(tokens, Wg, bg);
    expert_kernel<<<BB * KK, 1024>>>(tokens, W1, b1);
    out_kernel<<<BB * KK, CC>>>(W2, b2, out);
    if (out_size >= BB * KK * CC + 2) fin_kernel<<<1, 256>>>(out);
}

// round 5
// speedup vs baseline: 3.6776x; 3.6776x over previous
#include <cuda_runtime.h>
#include <cuda_bf16.h>
#include <math.h>
#include <stdint.h>

#define BB 16
#define NN 4096
#define CC 256
#define KK 8
#define EPSF 1e-6f
#define RATIOF 0.1f
#define NTOK (BB*NN)          // 65536
#define GATE_BLOCKS (NTOK/8)  // 8192

// ---------------- scratch globals (no allocs allowed) ----------------
__device__ float          g_geno[BB*KK];
__device__ unsigned short g_route_e[NTOK];     // e0 | e1<<8
__device__ float2         g_route_w[NTOK];     // w0, w1
__device__ float          g_conf[GATE_BLOCKS];
__device__ int            g_usage[KK];
__device__ float          g_hacc[BB*KK*CC];    // sum_n w * relu(tok@W1^T+b1)
__device__ float          g_mass[BB*KK];
__device__ unsigned short g_list[BB*KK][NN];   // compact token ids per (b,k)
__device__ float          g_wt[BB*KK][NN];     // gate weight per routed token
__device__ int            g_cnt[BB*KK];

// ---------------- geno term + usage reset ----------------
__global__ void geno_kernel(const float* __restrict__ geno_vec,
                            const float* __restrict__ Wgg,
                            const float* __restrict__ bgg) {
    int t = threadIdx.x;            // 128 threads = B*K
    int b = t / KK, k = t % KK;
    const float* g = geno_vec + b * CC;
    const float* w = Wgg + k * CC;
    float s = 0.f;
#pragma unroll 8
    for (int i = 0; i < CC; i++) s += g[i] * w[i];
    g_geno[t] = RATIOF * (s + bgg[k]);
    if (t < KK) g_usage[t] = 0;
}

// ---------------- gate: logits, top-2, softmax ----------------
__global__ void gate_kernel(const float* __restrict__ tokens,
                            const float* __restrict__ Wg,
                            const float* __restrict__ bg) {
    __shared__ float4 sWg[KK * 64];   // 8KB
    __shared__ float  sconf[8];
    int tid = threadIdx.x;
    for (int i = tid; i < KK * 64; i += 256) sWg[i] = ((const float4*)Wg)[i];
    __syncthreads();

    int warp = tid >> 5, lane = tid & 31;
    int t = blockIdx.x * 8 + warp;
    int b = t >> 12;

    const float4* tok4 = (const float4*)(tokens + (size_t)t * CC);
    float acc[KK];
#pragma unroll
    for (int k = 0; k < KK; k++) acc[k] = 0.f;
#pragma unroll
    for (int i = 0; i < 2; i++) {
        float4 tv = tok4[i * 32 + lane];
#pragma unroll
        for (int k = 0; k < KK; k++) {
            float4 w = sWg[k * 64 + i * 32 + lane];
            acc[k] += tv.x * w.x + tv.y * w.y + tv.z * w.z + tv.w * w.w;
        }
    }
#pragma unroll
    for (int k = 0; k < KK; k++) {
#pragma unroll
        for (int off = 16; off; off >>= 1)
            acc[k] += __shfl_xor_sync(0xffffffffu, acc[k], off);
    }
    if (lane == 0) {
        float lg[KK];
#pragma unroll
        for (int k = 0; k < KK; k++) lg[k] = acc[k] + bg[k] + g_geno[b * KK + k];
        int i0 = 0; float v0 = lg[0];
#pragma unroll
        for (int k = 1; k < KK; k++) if (lg[k] > v0) { v0 = lg[k]; i0 = k; }
        float v1 = -1e30f; int i1 = 0;
#pragma unroll
        for (int k = 0; k < KK; k++)
            if (k != i0 && lg[k] > v1) { v1 = lg[k]; i1 = k; }
        float e  = expf(v1 - v0);
        float w0 = 1.f / (1.f + e);
        float w1 = e / (1.f + e);
        w0 = fmaxf(w0, EPSF); w1 = fmaxf(w1, EPSF);
        float s = w0 + w1; w0 /= s; w1 /= s;
        g_route_e[t] = (unsigned short)(i0 | (i1 << 8));
        g_route_w[t] = make_float2(w0, w1);
        atomicAdd(&g_usage[i0], 1);
        atomicAdd(&g_usage[i1], 1);
        sconf[warp] = v0 - v1;
    }
    __syncthreads();
    if (tid == 0) {
        float cs = 0.f;
#pragma unroll
        for (int w = 0; w < 8; w++) cs += sconf[w];
        g_conf[blockIdx.x] = cs;
    }
}

// ---------------- per-(b,k) token compaction + mass ----------------
__global__ void compact_kernel() {
    int bk = blockIdx.x;           // 128 blocks, 1 warp
    int b = bk >> 3, k = bk & 7;
    int lane = threadIdx.x;
    int cnt = 0;
    float mass = 0.f;
    for (int base = 0; base < NN; base += 32) {
        int n = base + lane;
        unsigned short e = g_route_e[b * NN + n];
        float2 wv = g_route_w[b * NN + n];
        bool m0 = (e & 0xff) == k;
        bool m1 = (e >> 8)   == k;
        bool hit = m0 || m1;
        unsigned bal = __ballot_sync(0xffffffffu, hit);
        if (hit) {
            int pos = cnt + __popc(bal & ((1u << lane) - 1u));
            g_list[bk][pos] = (unsigned short)n;
            float w = m0 ? wv.x : wv.y;
            g_wt[bk][pos]   = w;
            mass += w;
        }
        cnt += __popc(bal);
    }
#pragma unroll
    for (int off = 16; off; off >>= 1) mass += __shfl_xor_sync(0xffffffffu, mass, off);
    if (lane == 0) { g_cnt[bk] = cnt; g_mass[bk] = mass; }
}

// ================= expert layer-1: mma.sync bf16x3 =================
// 256 blocks = (b, k, half). 256 threads = 8 warps.
// GEMM per block: X[cnt x 256] @ W1half^T[256 x 128], fused weighted-relu reduce.
// SMEM layout (padded stride 264 halves = 528 B/row, conflict-free):
//   sBh [128 x 264 bf16]   W1 half, hi part
//   sBl [128 x 264 bf16]   W1 half, lo part
//   sAh [ 64 x 264 bf16]   token tile, hi
//   sAl [ 64 x 264 bf16]   token tile, lo
//   swt [64 f32], sb1 [128 f32]
#define ROWB 528                     // bytes per padded row
#define OFF_BH 0
#define OFF_BL (128 * ROWB)
#define OFF_AH (2 * 128 * ROWB)
#define OFF_AL (2 * 128 * ROWB + 64 * ROWB)
#define OFF_WT (2 * 128 * ROWB + 2 * 64 * ROWB)
#define OFF_B1 (OFF_WT + 256)
#define SM_TOTAL (OFF_B1 + 512 + 16)

__device__ __forceinline__ uint32_t pack_bf2(float a, float b) {
    unsigned short ha = __bfloat16_as_ushort(__float2bfloat16(a));
    unsigned short hb = __bfloat16_as_ushort(__float2bfloat16(b));
    return (uint32_t)ha | ((uint32_t)hb << 16);
}
__device__ __forceinline__ void split2(float x, float y, uint32_t& hi, uint32_t& lo) {
    float hx = __bfloat162float(__float2bfloat16(x));
    float hy = __bfloat162float(__float2bfloat16(y));
    hi = pack_bf2(x, y);
    lo = pack_bf2(x - hx, y - hy);
}
__device__ __forceinline__ void mma16816(float* c, const uint32_t* a, const uint32_t* b) {
    asm volatile("mma.sync.aligned.m16n8k16.row.col.f32.bf16.bf16.f32 "
        "{%0,%1,%2,%3}, {%4,%5,%6,%7}, {%8,%9}, {%0,%1,%2,%3};"
        : "+f"(c[0]), "+f"(c[1]), "+f"(c[2]), "+f"(c[3])
        : "r"(a[0]), "r"(a[1]), "r"(a[2]), "r"(a[3]), "r"(b[0]), "r"(b[1]));
}

__global__ void __launch_bounds__(256, 1)
expert_kernel(const float* __restrict__ tokens,
              const float* __restrict__ W1,
              const float* __restrict__ b1) {
    extern __shared__ char sm[];
    int tid = threadIdx.x;
    int warp = tid >> 5, lane = tid & 31;

    int bid = blockIdx.x;
    int b = bid >> 4, k = (bid >> 1) & 7, half = bid & 1;
    int bk = b * KK + k;

    // ---- stage W1 half as bf16 hi/lo ----
    {
        int row = tid >> 1, seg = tid & 1;      // 128 rows x 2 segments of 128
        const float4* src = (const float4*)(W1 + (size_t)k * CC * CC
                                            + (size_t)(half * 128 + row) * CC + seg * 128);
        char* ph = sm + OFF_BH + row * ROWB + seg * 256;
        char* pl = sm + OFF_BL + row * ROWB + seg * 256;
#pragma unroll 8
        for (int j = 0; j < 32; j++) {
            float4 v = src[j];
            uint32_t h0, l0, h1, l1;
            split2(v.x, v.y, h0, l0);
            split2(v.z, v.w, h1, l1);
            *(uint32_t*)(ph + j * 8)     = h0;
            *(uint32_t*)(ph + j * 8 + 4) = h1;
            *(uint32_t*)(pl + j * 8)     = l0;
            *(uint32_t*)(pl + j * 8 + 4) = l1;
        }
        if (tid < 128) ((float*)(sm + OFF_B1))[tid] = b1[k * CC + half * 128 + tid];
    }

    int cnt = g_cnt[bk];
    int ntiles = (cnt + 63) >> 6;

    float acc[4][2][4];
#pragma unroll
    for (int mt = 0; mt < 4; mt++)
#pragma unroll
        for (int nt = 0; nt < 2; nt++)
#pragma unroll
            for (int j = 0; j < 4; j++) acc[mt][nt][j] = 0.f;
    float colsum[2][2] = {{0.f, 0.f}, {0.f, 0.f}};

    const float* swt = (const float*)(sm + OFF_WT);
    const float* sb1 = (const float*)(sm + OFF_B1);

    for (int tile = 0; tile < ntiles; tile++) {
        __syncthreads();     // previous K-loop readers done (also covers W1 staging)
        // ---- stage 64-token tile (gather + split) ----
        {
            int row = tid >> 2, seg = tid & 3;  // 64 rows x 4 segments of 64
            int tslot = tile * 64 + row;
            bool valid = tslot < cnt;
            int n = valid ? (int)g_list[bk][tslot] : 0;
            if (seg == 0) ((float*)(sm + OFF_WT))[row] = valid ? g_wt[bk][tslot] : 0.f;
            const float4* src = (const float4*)(tokens + ((size_t)b * NN + n) * CC + seg * 64);
            char* ph = sm + OFF_AH + row * ROWB + seg * 128;
            char* pl = sm + OFF_AL + row * ROWB + seg * 128;
#pragma unroll 4
            for (int j = 0; j < 16; j++) {
                float4 v = src[j];
                uint32_t h0, l0, h1, l1;
                split2(v.x, v.y, h0, l0);
                split2(v.z, v.w, h1, l1);
                *(uint32_t*)(ph + j * 8)     = h0;
                *(uint32_t*)(ph + j * 8 + 4) = h1;
                *(uint32_t*)(pl + j * 8)     = l0;
                *(uint32_t*)(pl + j * 8 + 4) = l1;
            }
        }
        __syncthreads();

        // ---- K loop: 16 steps of k16 ----
#pragma unroll 4
        for (int ks = 0; ks < 16; ks++) {
            int kk = ks * 16 + (lane & 3) * 2;      // element col for this lane
            uint32_t bh[2][2], bl[2][2];
#pragma unroll
            for (int nt = 0; nt < 2; nt++) {
                int n = warp * 16 + nt * 8 + (lane >> 2);
                const char* pb = sm + n * ROWB + kk * 2;
                bh[nt][0] = *(const uint32_t*)(pb + OFF_BH);
                bh[nt][1] = *(const uint32_t*)(pb + OFF_BH + 16);
                bl[nt][0] = *(const uint32_t*)(pb + OFF_BL);
                bl[nt][1] = *(const uint32_t*)(pb + OFF_BL + 16);
            }
#pragma unroll
            for (int mt = 0; mt < 4; mt++) {
                int m = mt * 16 + (lane >> 2);
                const char* pa = sm + m * ROWB + kk * 2;
                uint32_t ah[4], al[4];
                ah[0] = *(const uint32_t*)(pa + OFF_AH);
                ah[1] = *(const uint32_t*)(pa + OFF_AH + 8 * ROWB);
                ah[2] = *(const uint32_t*)(pa + OFF_AH + 16);
                ah[3] = *(const uint32_t*)(pa + OFF_AH + 8 * ROWB + 16);
                al[0] = *(const uint32_t*)(pa + OFF_AL);
                al[1] = *(const uint32_t*)(pa + OFF_AL + 8 * ROWB);
                al[2] = *(const uint32_t*)(pa + OFF_AL + 16);
                al[3] = *(const uint32_t*)(pa + OFF_AL + 8 * ROWB + 16);
#pragma unroll
                for (int nt = 0; nt < 2; nt++) {
                    mma16816(acc[mt][nt], ah, bh[nt]);
                    mma16816(acc[mt][nt], ah, bl[nt]);
                    mma16816(acc[mt][nt], al, bh[nt]);
                }
            }
        }

        // ---- fused epilogue for this M-tile ----
#pragma unroll
        for (int mt = 0; mt < 4; mt++) {
            int r0 = mt * 16 + (lane >> 2);
            float w0 = swt[r0], w1 = swt[r0 + 8];
#pragma unroll
            for (int nt = 0; nt < 2; nt++) {
                int c0 = warp * 16 + nt * 8 + (lane & 3) * 2;
                float bb0 = sb1[c0], bb1 = sb1[c0 + 1];
                colsum[nt][0] += w0 * fmaxf(acc[mt][nt][0] + bb0, 0.f)
                               + w1 * fmaxf(acc[mt][nt][2] + bb0, 0.f);
                colsum[nt][1] += w0 * fmaxf(acc[mt][nt][1] + bb1, 0.f)
                               + w1 * fmaxf(acc[mt][nt][3] + bb1, 0.f);
#pragma unroll
                for (int j = 0; j < 4; j++) acc[mt][nt][j] = 0.f;
            }
        }
    }

    // ---- reduce colsums across the 8 row-group lanes, write ----
#pragma unroll
    for (int nt = 0; nt < 2; nt++)
#pragma unroll
        for (int j = 0; j < 2; j++) {
#pragma unroll
            for (int off = 4; off <= 16; off <<= 1)
                colsum[nt][j] += __shfl_xor_sync(0xffffffffu, colsum[nt][j], off);
        }
    if (lane < 4) {
#pragma unroll
        for (int nt = 0; nt < 2; nt++) {
            int c = warp * 16 + nt * 8 + lane * 2;
            g_hacc[bk * CC + half * 128 + c]     = colsum[nt][0];
            g_hacc[bk * CC + half * 128 + c + 1] = colsum[nt][1];
        }
    }
}

// ---------------- layer-2 + normalize -> centers ----------------
__global__ void out_kernel(const float* __restrict__ W2,
                           const float* __restrict__ b2,
                           float* __restrict__ out) {
    __shared__ float sh[CC];
    int bk = blockIdx.x;
    int k = bk & 7;
    int c = threadIdx.x;
    sh[c] = g_hacc[bk * CC + c];
    __syncthreads();
    const float4* w4 = (const float4*)(W2 + ((size_t)k * CC + c) * CC);
    float s = 0.f;
#pragma unroll 8
    for (int j = 0; j < CC / 4; j++) {
        float4 w = w4[j];
        s += sh[4*j] * w.x + sh[4*j+1] * w.y + sh[4*j+2] * w.z + sh[4*j+3] * w.w;
    }
    float mass = g_mass[bk];
    s += mass * b2[k * CC + c];
    s /= fmaxf(mass, EPSF);
    out[bk * CC + c] = s;
}

// ---------------- scalars ----------------
__global__ void fin_kernel(float* __restrict__ out) {
    __shared__ float sred[256];
    int tid = threadIdx.x;
    float s = 0.f;
    for (int i = tid; i < GATE_BLOCKS; i += 256) s += g_conf[i];
    sred[tid] = s;
    __syncthreads();
    for (int off = 128; off; off >>= 1) {
        if (tid < off) sred[tid] += sred[tid + off];
        __syncthreads();
    }
    if (tid == 0) {
        float rc = sred[0] / (float)NTOK;
        float u[KK]; float mean = 0.f;
#pragma unroll
        for (int k = 0; k < KK; k++) { u[k] = (float)g_usage[k] / (float)NTOK; mean += u[k]; }
        mean /= (float)KK;
        float var = 0.f;
#pragma unroll
        for (int k = 0; k < KK; k++) { float d = u[k] - mean; var += d * d; }
        var /= (float)KK;
        float den = mean + EPSF;
        out[BB * KK * CC]     = var / (den * den);
        out[BB * KK * CC + 1] = rc;
    }
}

// ---------------- launch ----------------
extern "C" void kernel_launch(void* const* d_in, const int* in_sizes, int n_in,
                              void* d_out, int out_size) {
    const float* tokens = (const float*)d_in[0];
    const float* geno   = (const float*)d_in[1];
    const float* Wg     = (const float*)d_in[2];
    const float* bg     = (const float*)d_in[3];
    const float* Wgg    = (const float*)d_in[4];
    const float* bgg    = (const float*)d_in[5];
    const float* W1     = (const float*)d_in[6];
    const float* b1     = (const float*)d_in[7];
    const float* W2     = (const float*)d_in[8];
    const float* b2     = (const float*)d_in[9];
    float* out = (float*)d_out;

    static int smem_set = 0;
    if (!smem_set) {
        cudaFuncSetAttribute(expert_kernel, cudaFuncAttributeMaxDynamicSharedMemorySize, SM_TOTAL);
        smem_set = 1;
    }

    geno_kernel<<<1, 128>>>(geno, Wgg, bgg);
    gate_kernel<<<GATE_BLOCKS, 256>>>(tokens, Wg, bg);
    compact_kernel<<<BB * KK, 32>>>();
    expert_kernel<<<BB * KK * 2, 256, SM_TOTAL>>>(tokens, W1, b1);
    out_kernel<<<BB * KK, CC>>>(W2, b2, out);
    if (out_size >= BB * KK * CC + 2) fin_kernel<<<1, 256>>>(out);
}

// round 6
// speedup vs baseline: 6.6248x; 1.8014x over previous
#include <cuda_runtime.h>
#include <cuda_bf16.h>
#include <math.h>
#include <stdint.h>

#define BB 16
#define NN 4096
#define CC 256
#define KK 8
#define EPSF 1e-6f
#define RATIOF 0.1f
#define NTOK (BB*NN)          // 65536
#define GATE_BLOCKS (NTOK/8)  // 8192

// ---------------- scratch globals ----------------
__device__ float          g_geno[BB*KK];
__device__ unsigned short g_route_e[NTOK];     // e0 | e1<<8
__device__ float2         g_route_w[NTOK];     // w0, w1
__device__ float          g_conf[GATE_BLOCKS];
__device__ int            g_usage[KK];
__device__ float          g_hacc[BB*KK*CC];    // sum_n w * relu(tok@W1^T+b1)
__device__ float          g_mass[BB*KK];
__device__ unsigned short g_list[BB*KK][NN];   // compact token ids per (b,k)
__device__ float          g_wt[BB*KK][NN];
__device__ int            g_cnt[BB*KK];

// ---------------- geno term + usage reset ----------------
__global__ void geno_kernel(const float* __restrict__ geno_vec,
                            const float* __restrict__ Wgg,
                            const float* __restrict__ bgg) {
    int t = threadIdx.x;            // 128 threads = B*K
    int b = t / KK, k = t % KK;
    const float* g = geno_vec + b * CC;
    const float* w = Wgg + k * CC;
    float s = 0.f;
#pragma unroll 8
    for (int i = 0; i < CC; i++) s += g[i] * w[i];
    g_geno[t] = RATIOF * (s + bgg[k]);
    if (t < KK) g_usage[t] = 0;
}

// ---------------- gate: logits, top-2, softmax ----------------
__global__ void gate_kernel(const float* __restrict__ tokens,
                            const float* __restrict__ Wg,
                            const float* __restrict__ bg) {
    __shared__ float4 sWg[KK * 64];   // 8KB
    __shared__ float  sconf[8];
    int tid = threadIdx.x;
    for (int i = tid; i < KK * 64; i += 256) sWg[i] = ((const float4*)Wg)[i];
    __syncthreads();

    int warp = tid >> 5, lane = tid & 31;
    int t = blockIdx.x * 8 + warp;
    int b = t >> 12;

    const float4* tok4 = (const float4*)(tokens + (size_t)t * CC);
    float acc[KK];
#pragma unroll
    for (int k = 0; k < KK; k++) acc[k] = 0.f;
#pragma unroll
    for (int i = 0; i < 2; i++) {
        float4 tv = tok4[i * 32 + lane];
#pragma unroll
        for (int k = 0; k < KK; k++) {
            float4 w = sWg[k * 64 + i * 32 + lane];
            acc[k] += tv.x * w.x + tv.y * w.y + tv.z * w.z + tv.w * w.w;
        }
    }
#pragma unroll
    for (int k = 0; k < KK; k++) {
#pragma unroll
        for (int off = 16; off; off >>= 1)
            acc[k] += __shfl_xor_sync(0xffffffffu, acc[k], off);
    }
    if (lane == 0) {
        float lg[KK];
#pragma unroll
        for (int k = 0; k < KK; k++) lg[k] = acc[k] + bg[k] + g_geno[b * KK + k];
        int i0 = 0; float v0 = lg[0];
#pragma unroll
        for (int k = 1; k < KK; k++) if (lg[k] > v0) { v0 = lg[k]; i0 = k; }
        float v1 = -1e30f; int i1 = 0;
#pragma unroll
        for (int k = 0; k < KK; k++)
            if (k != i0 && lg[k] > v1) { v1 = lg[k]; i1 = k; }
        float e  = expf(v1 - v0);
        float w0 = 1.f / (1.f + e);
        float w1 = e / (1.f + e);
        w0 = fmaxf(w0, EPSF); w1 = fmaxf(w1, EPSF);
        float s = w0 + w1; w0 /= s; w1 /= s;
        g_route_e[t] = (unsigned short)(i0 | (i1 << 8));
        g_route_w[t] = make_float2(w0, w1);
        atomicAdd(&g_usage[i0], 1);
        atomicAdd(&g_usage[i1], 1);
        sconf[warp] = v0 - v1;
    }
    __syncthreads();
    if (tid == 0) {
        float cs = 0.f;
#pragma unroll
        for (int w = 0; w < 8; w++) cs += sconf[w];
        g_conf[blockIdx.x] = cs;
    }
}

// ---------------- per-(b,k) compaction: 8 warps, 2-pass deterministic ----------------
__global__ void compact_kernel() {
    __shared__ int   scnt[8];
    __shared__ float smass[8];
    __shared__ int   soff[8];
    int bk = blockIdx.x;
    int b = bk >> 3, k = bk & 7;
    int tid = threadIdx.x;
    int warp = tid >> 5, lane = tid & 31;

    // pass 1: count + mass over this warp's 512-token range
    int cnt = 0; float mass = 0.f;
    int base0 = warp * 512;
    for (int i = 0; i < 16; i++) {
        int n = base0 + i * 32 + lane;
        unsigned short e = g_route_e[b * NN + n];
        float2 wv = g_route_w[b * NN + n];
        bool m0 = (e & 0xff) == k;
        bool m1 = (e >> 8)   == k;
        bool hit = m0 || m1;
        unsigned bal = __ballot_sync(0xffffffffu, hit);
        cnt += __popc(bal);
        if (hit) mass += m0 ? wv.x : wv.y;
    }
#pragma unroll
    for (int off = 16; off; off >>= 1) mass += __shfl_xor_sync(0xffffffffu, mass, off);
    if (lane == 0) { scnt[warp] = cnt; smass[warp] = mass; }
    __syncthreads();
    if (tid == 0) {
        int run = 0; float msum = 0.f;
#pragma unroll
        for (int w = 0; w < 8; w++) { soff[w] = run; run += scnt[w]; msum += smass[w]; }
        g_cnt[bk] = run;
        g_mass[bk] = msum;
    }
    __syncthreads();

    // pass 2: write
    int pos = soff[warp];
    for (int i = 0; i < 16; i++) {
        int n = base0 + i * 32 + lane;
        unsigned short e = g_route_e[b * NN + n];
        float2 wv = g_route_w[b * NN + n];
        bool m0 = (e & 0xff) == k;
        bool m1 = (e >> 8)   == k;
        bool hit = m0 || m1;
        unsigned bal = __ballot_sync(0xffffffffu, hit);
        if (hit) {
            int p = pos + __popc(bal & ((1u << lane) - 1u));
            g_list[bk][p] = (unsigned short)n;
            g_wt[bk][p]   = m0 ? wv.x : wv.y;
        }
        pos += __popc(bal);
    }
}

// ================= expert layer-1: mma.sync bf16x2 (A plain, B hi/lo), LDSM =================
// 256 blocks = (b, k, half). 512 threads = 16 warps: warpN=warp&7 (16 cols), warpM=warp>>3 (32 rows).
// SMEM (ROWB=528 padded): Bh[128], Bl[128], A double-buffered [2][64], wt[2][64], b1[128], red[128].
#define ROWB 528
#define OFF_BH 0
#define OFF_BL (128 * ROWB)                         // 67584
#define BL_DELTA (OFF_BL - OFF_BH)
#define OFF_A0 (2 * 128 * ROWB)                     // 135168
#define OFF_A1 (OFF_A0 + 64 * ROWB)                 // 168960
#define OFF_WT (OFF_A1 + 64 * ROWB)                 // 202752 : 2*64 floats
#define OFF_B1 (OFF_WT + 512)                       // 128 floats
#define OFF_RED (OFF_B1 + 512)                      // 128 floats
#define SM_TOTAL (OFF_RED + 512 + 16)

__device__ __forceinline__ uint32_t smem_u32(const void* p) {
    uint32_t a;
    asm("{ .reg .u64 t; cvta.to.shared.u64 t, %1; cvt.u32.u64 %0, t; }" : "=r"(a) : "l"(p));
    return a;
}
__device__ __forceinline__ uint32_t cvt_bf16x2(float lo, float hi) {
    uint32_t r;
    asm("cvt.rn.bf16x2.f32 %0, %1, %2;" : "=r"(r) : "f"(hi), "f"(lo));
    return r;
}
__device__ __forceinline__ uint32_t pack_bf2(float a, float b) { return cvt_bf16x2(a, b); }
__device__ __forceinline__ void split2(float x, float y, uint32_t& hi, uint32_t& lo) {
    float hx = __bfloat162float(__float2bfloat16(x));
    float hy = __bfloat162float(__float2bfloat16(y));
    hi = pack_bf2(x, y);
    lo = pack_bf2(x - hx, y - hy);
}
__device__ __forceinline__ void mma16816(float* c, const uint32_t* a, const uint32_t* b) {
    asm volatile("mma.sync.aligned.m16n8k16.row.col.f32.bf16.bf16.f32 "
        "{%0,%1,%2,%3}, {%4,%5,%6,%7}, {%8,%9}, {%0,%1,%2,%3};"
        : "+f"(c[0]), "+f"(c[1]), "+f"(c[2]), "+f"(c[3])
        : "r"(a[0]), "r"(a[1]), "r"(a[2]), "r"(a[3]), "r"(b[0]), "r"(b[1]));
}
#define LDSM4(r, addr) \
    asm volatile("ldmatrix.sync.aligned.m8n8.x4.shared.b16 {%0,%1,%2,%3}, [%4];" \
        : "=r"((r)[0]), "=r"((r)[1]), "=r"((r)[2]), "=r"((r)[3]) : "r"(addr))

__global__ void __launch_bounds__(512, 1)
expert_kernel(const float* __restrict__ tokens,
              const float* __restrict__ W1,
              const float* __restrict__ b1) {
    extern __shared__ char sm[];
    uint32_t smemu = smem_u32(sm);
    int tid = threadIdx.x;
    int warp = tid >> 5, lane = tid & 31;
    int warpN = warp & 7, warpM = warp >> 3;

    int bid = blockIdx.x;
    int b = bid >> 4, k = (bid >> 1) & 7, half = bid & 1;
    int bk = b * KK + k;

    // ---- stage W1 half as bf16 hi/lo ----
    {
        int row = tid >> 2, q = tid & 3;
        const float4* src = (const float4*)(W1 + (size_t)k * CC * CC
                                            + (size_t)(half * 128 + row) * CC);
        char* rh = sm + OFF_BH + row * ROWB;
        char* rl = sm + OFF_BL + row * ROWB;
#pragma unroll 4
        for (int j = 0; j < 16; j++) {
            int cc = j * 4 + q;
            float4 v = src[cc];
            uint32_t h0, l0, h1, l1;
            split2(v.x, v.y, h0, l0);
            split2(v.z, v.w, h1, l1);
            *(uint2*)(rh + cc * 8) = make_uint2(h0, h1);
            *(uint2*)(rl + cc * 8) = make_uint2(l0, l1);
        }
        if (tid < 128) ((float*)(sm + OFF_B1))[tid] = b1[k * CC + half * 128 + tid];
    }

    int cnt = g_cnt[bk];
    int ntiles = (cnt + 63) >> 6;

    // ---- prologue: stage tile 0 into buf 0 ----
    {
        int row = tid >> 3, seg = tid & 7;
        int slot = row;
        bool valid = slot < cnt;
        int n = valid ? (int)g_list[bk][slot] : 0;
        if (seg == 0) ((float*)(sm + OFF_WT))[row] = valid ? g_wt[bk][slot] : 0.f;
        const float4* src = (const float4*)(tokens + ((size_t)b * NN + n) * CC);
        char* ra = sm + OFF_A0 + row * ROWB;
#pragma unroll
        for (int j = 0; j < 8; j++) {
            int cc = j * 8 + seg;
            float4 v = src[cc];
            *(uint2*)(ra + cc * 8) = make_uint2(pack_bf2(v.x, v.y), pack_bf2(v.z, v.w));
        }
    }
    __syncthreads();

    float acc[2][2][4];
#pragma unroll
    for (int mt = 0; mt < 2; mt++)
#pragma unroll
        for (int nt = 0; nt < 2; nt++)
#pragma unroll
            for (int j = 0; j < 4; j++) acc[mt][nt][j] = 0.f;
    float colsum[2][2] = {{0.f, 0.f}, {0.f, 0.f}};

    const float* sb1 = (const float*)(sm + OFF_B1);

    // per-thread invariant LDSM base addresses
    uint32_t aA_row = (uint32_t)((warpM * 32 + (lane & 15)) * ROWB + ((lane & 16) ? 16 : 0));
    uint32_t aB_base = smemu + OFF_BH
        + (uint32_t)((warpN * 16 + (lane & 7) + ((lane & 16) ? 8 : 0)) * ROWB
                     + ((lane & 8) ? 16 : 0));
    int prow = tid >> 3, pseg = tid & 7;

    for (int t = 0; t < ntiles; t++) {
        int cur = t & 1;
        uint32_t aA_base = smemu + (cur ? OFF_A1 : OFF_A0) + aA_row;

        // prefetch next tile (LDG + convert -> 16 regs)
        uint2 pu[8];
        float pwt = 0.f;
        bool havenext = (t + 1 < ntiles);
        if (havenext) {
            int slot = (t + 1) * 64 + prow;
            bool valid = slot < cnt;
            int n = valid ? (int)g_list[bk][slot] : 0;
            if (pseg == 0) pwt = valid ? g_wt[bk][slot] : 0.f;
            const float4* src = (const float4*)(tokens + ((size_t)b * NN + n) * CC);
#pragma unroll
            for (int j = 0; j < 8; j++) {
                float4 v = src[j * 8 + pseg];
                pu[j] = make_uint2(pack_bf2(v.x, v.y), pack_bf2(v.z, v.w));
            }
        }

        // ---- K loop: 16 steps, LDSM + 8 HMMA each ----
#pragma unroll
        for (int ks = 0; ks < 16; ks++) {
            uint32_t kb = (uint32_t)(ks * 32);
            uint32_t a0[4], a1[4], bh[4], bl[4];
            LDSM4(a0, aA_base + kb);
            LDSM4(a1, aA_base + 16 * ROWB + kb);
            LDSM4(bh, aB_base + kb);
            LDSM4(bl, aB_base + BL_DELTA + kb);
            mma16816(acc[0][0], a0, bh + 0);
            mma16816(acc[0][1], a0, bh + 2);
            mma16816(acc[1][0], a1, bh + 0);
            mma16816(acc[1][1], a1, bh + 2);
            mma16816(acc[0][0], a0, bl + 0);
            mma16816(acc[0][1], a0, bl + 2);
            mma16816(acc[1][0], a1, bl + 0);
            mma16816(acc[1][1], a1, bl + 2);
        }

        // ---- fused epilogue ----
        {
            const float* swt = (const float*)(sm + OFF_WT) + cur * 64;
#pragma unroll
            for (int mt = 0; mt < 2; mt++) {
                int r0 = warpM * 32 + mt * 16 + (lane >> 2);
                float w0 = swt[r0], w1 = swt[r0 + 8];
#pragma unroll
                for (int nt = 0; nt < 2; nt++) {
                    int c0 = warpN * 16 + nt * 8 + (lane & 3) * 2;
                    float bb0 = sb1[c0], bb1 = sb1[c0 + 1];
                    colsum[nt][0] += w0 * fmaxf(acc[mt][nt][0] + bb0, 0.f)
                                   + w1 * fmaxf(acc[mt][nt][2] + bb0, 0.f);
                    colsum[nt][1] += w0 * fmaxf(acc[mt][nt][1] + bb1, 0.f)
                                   + w1 * fmaxf(acc[mt][nt][3] + bb1, 0.f);
#pragma unroll
                    for (int j = 0; j < 4; j++) acc[mt][nt][j] = 0.f;
                }
            }
        }

        // ---- commit prefetched tile into the other buffer ----
        if (havenext) {
            char* ra = sm + (cur ? OFF_A0 : OFF_A1) + prow * ROWB;
#pragma unroll
            for (int j = 0; j < 8; j++)
                *(uint2*)(ra + (j * 8 + pseg) * 8) = pu[j];
            if (pseg == 0)
                ((float*)(sm + OFF_WT))[(1 - cur) * 64 + prow] = pwt;
        }
        __syncthreads();
    }

    // ---- reduce over lane row-groups, then across warpM, write ----
#pragma unroll
    for (int nt = 0; nt < 2; nt++)
#pragma unroll
        for (int j = 0; j < 2; j++) {
#pragma unroll
            for (int off = 4; off <= 16; off <<= 1)
                colsum[nt][j] += __shfl_xor_sync(0xffffffffu, colsum[nt][j], off);
        }
    float* sred = (float*)(sm + OFF_RED);
    if (warpM == 1 && lane < 4) {
#pragma unroll
        for (int nt = 0; nt < 2; nt++) {
            int c = warpN * 16 + nt * 8 + lane * 2;
            sred[c]     = colsum[nt][0];
            sred[c + 1] = colsum[nt][1];
        }
    }
    __syncthreads();
    if (warpM == 0 && lane < 4) {
#pragma unroll
        for (int nt = 0; nt < 2; nt++) {
            int c = warpN * 16 + nt * 8 + lane * 2;
            g_hacc[bk * CC + half * 128 + c]     = colsum[nt][0] + sred[c];
            g_hacc[bk * CC + half * 128 + c + 1] = colsum[nt][1] + sred[c + 1];
        }
    }
}

// ---------------- layer-2 + normalize -> centers ----------------
__global__ void out_kernel(const float* __restrict__ W2,
                           const float* __restrict__ b2,
                           float* __restrict__ out) {
    __shared__ float sh[CC];
    int bk = blockIdx.x;
    int k = bk & 7;
    int c = threadIdx.x;
    sh[c] = g_hacc[bk * CC + c];
    __syncthreads();
    const float4* w4 = (const float4*)(W2 + ((size_t)k * CC + c) * CC);
    float p0 = 0.f, p1 = 0.f, p2 = 0.f, p3 = 0.f;
#pragma unroll 16
    for (int j = 0; j < CC / 4; j++) {
        float4 w = w4[j];
        float* shj = sh + 4 * j;
        p0 += shj[0] * w.x;
        p1 += shj[1] * w.y;
        p2 += shj[2] * w.z;
        p3 += shj[3] * w.w;
    }
    float s = (p0 + p1) + (p2 + p3);
    float mass = g_mass[bk];
    s += mass * b2[k * CC + c];
    s /= fmaxf(mass, EPSF);
    out[bk * CC + c] = s;
}

// ---------------- scalars ----------------
__global__ void fin_kernel(float* __restrict__ out) {
    __shared__ float sred[256];
    int tid = threadIdx.x;
    float s = 0.f;
    for (int i = tid; i < GATE_BLOCKS; i += 256) s += g_conf[i];
    sred[tid] = s;
    __syncthreads();
    for (int off = 128; off; off >>= 1) {
        if (tid < off) sred[tid] += sred[tid + off];
        __syncthreads();
    }
    if (tid == 0) {
        float rc = sred[0] / (float)NTOK;
        float u[KK]; float mean = 0.f;
#pragma unroll
        for (int k = 0; k < KK; k++) { u[k] = (float)g_usage[k] / (float)NTOK; mean += u[k]; }
        mean /= (float)KK;
        float var = 0.f;
#pragma unroll
        for (int k = 0; k < KK; k++) { float d = u[k] - mean; var += d * d; }
        var /= (float)KK;
        float den = mean + EPSF;
        out[BB * KK * CC]     = var / (den * den);
        out[BB * KK * CC + 1] = rc;
    }
}

// ---------------- launch ----------------
extern "C" void kernel_launch(void* const* d_in, const int* in_sizes, int n_in,
                              void* d_out, int out_size) {
    const float* tokens = (const float*)d_in[0];
    const float* geno   = (const float*)d_in[1];
    const float* Wg     = (const float*)d_in[2];
    const float* bg     = (const float*)d_in[3];
    const float* Wgg    = (const float*)d_in[4];
    const float* bgg    = (const float*)d_in[5];
    const float* W1     = (const float*)d_in[6];
    const float* b1     = (const float*)d_in[7];
    const float* W2     = (const float*)d_in[8];
    const float* b2     = (const float*)d_in[9];
    float* out = (float*)d_out;

    cudaFuncSetAttribute(expert_kernel, cudaFuncAttributeMaxDynamicSharedMemorySize, SM_TOTAL);

    geno_kernel<<<1, 128>>>(geno, Wgg, bgg);
    gate_kernel<<<GATE_BLOCKS, 256>>>(tokens, Wg, bg);
    compact_kernel<<<BB * KK, 256>>>();
    expert_kernel<<<BB * KK * 2, 512, SM_TOTAL>>>(tokens, W1, b1);
    out_kernel<<<BB * KK, CC>>>(W2, b2, out);
    if (out_size >= BB * KK * CC + 2) fin_kernel<<<1, 256>>>(out);
}

// round 7
// speedup vs baseline: 8.5628x; 1.2925x over previous
#include <cuda_runtime.h>
#include <cuda_bf16.h>
#include <math.h>
#include <stdint.h>

#define BB 16
#define NN 4096
#define CC 256
#define KK 8
#define EPSF 1e-6f
#define RATIOF 0.1f
#define NTOK (BB*NN)          // 65536
#define GATE_BLOCKS (NTOK/16) // 4096 (16 tokens per block, 2 per warp)
#define NITEMS (BB*KK*2)      // 256 expert work items

// ---------------- scratch globals ----------------
__device__ float          g_geno[BB*KK];
__device__ unsigned short g_route_e[NTOK];     // e0 | e1<<8
__device__ float2         g_route_w[NTOK];     // w0, w1
__device__ float          g_conf[GATE_BLOCKS];
__device__ float          g_hacc[BB*KK*CC];    // sum_n w * relu(tok@W1^T+b1)
__device__ float          g_mass[BB*KK];
__device__ unsigned short g_list[BB*KK][NN];   // compact token ids per (b,k)
__device__ float          g_wt[BB*KK][NN];
__device__ int            g_cnt[BB*KK];
__device__ int            g_item;              // persistent-kernel work counter

// ---------------- geno term + work-counter reset ----------------
__global__ void geno_kernel(const float* __restrict__ geno_vec,
                            const float* __restrict__ Wgg,
                            const float* __restrict__ bgg) {
    int t = threadIdx.x;            // 128 threads = B*K
    int b = t / KK, k = t % KK;
    const float* g = geno_vec + b * CC;
    const float* w = Wgg + k * CC;
    float s = 0.f;
#pragma unroll 8
    for (int i = 0; i < CC; i++) s += g[i] * w[i];
    g_geno[t] = RATIOF * (s + bgg[k]);
    if (t == 0) g_item = 0;
}

// ---------------- gate: logits, top-2, softmax (2 tokens per warp) ----------------
__global__ void gate_kernel(const float* __restrict__ tokens,
                            const float* __restrict__ Wg,
                            const float* __restrict__ bg) {
    __shared__ float4 sWg[KK * 64];   // 8KB
    __shared__ float  sconf[16];
    int tid = threadIdx.x;
    for (int i = tid; i < KK * 64; i += 256) sWg[i] = ((const float4*)Wg)[i];
    __syncthreads();

    int warp = tid >> 5, lane = tid & 31;
    int t0 = blockIdx.x * 16 + warp * 2;      // two consecutive tokens
    int b = t0 >> 12;

    float acc[2][KK];
#pragma unroll
    for (int u = 0; u < 2; u++)
#pragma unroll
        for (int k = 0; k < KK; k++) acc[u][k] = 0.f;

#pragma unroll
    for (int i = 0; i < 2; i++) {
        float4 tv0 = ((const float4*)(tokens + (size_t)t0 * CC))[i * 32 + lane];
        float4 tv1 = ((const float4*)(tokens + (size_t)(t0 + 1) * CC))[i * 32 + lane];
#pragma unroll
        for (int k = 0; k < KK; k++) {
            float4 w = sWg[k * 64 + i * 32 + lane];
            acc[0][k] += tv0.x * w.x + tv0.y * w.y + tv0.z * w.z + tv0.w * w.w;
            acc[1][k] += tv1.x * w.x + tv1.y * w.y + tv1.z * w.z + tv1.w * w.w;
        }
    }
#pragma unroll
    for (int k = 0; k < KK; k++) {
#pragma unroll
        for (int off = 16; off; off >>= 1) {
            acc[0][k] += __shfl_xor_sync(0xffffffffu, acc[0][k], off);
            acc[1][k] += __shfl_xor_sync(0xffffffffu, acc[1][k], off);
        }
    }
    if (lane < 2) {
        int t = t0 + lane;
        float lg[KK];
#pragma unroll
        for (int k = 0; k < KK; k++) {
            float a = __shfl_sync(0x3u, acc[0][k], 0) * (lane == 0 ? 1.f : 0.f)
                    + __shfl_sync(0x3u, acc[1][k], 0) * (lane == 1 ? 1.f : 0.f);
            lg[k] = a + bg[k] + g_geno[b * KK + k];
        }
        int i0 = 0; float v0 = lg[0];
#pragma unroll
        for (int k = 1; k < KK; k++) if (lg[k] > v0) { v0 = lg[k]; i0 = k; }
        float v1 = -1e30f; int i1 = 0;
#pragma unroll
        for (int k = 0; k < KK; k++)
            if (k != i0 && lg[k] > v1) { v1 = lg[k]; i1 = k; }
        float e  = expf(v1 - v0);
        float w0 = 1.f / (1.f + e);
        float w1 = e / (1.f + e);
        w0 = fmaxf(w0, EPSF); w1 = fmaxf(w1, EPSF);
        float s = w0 + w1; w0 /= s; w1 /= s;
        g_route_e[t] = (unsigned short)(i0 | (i1 << 8));
        g_route_w[t] = make_float2(w0, w1);
        sconf[warp * 2 + lane] = v0 - v1;
    }
    __syncthreads();
    if (tid == 0) {
        float cs = 0.f;
#pragma unroll
        for (int w = 0; w < 16; w++) cs += sconf[w];
        g_conf[blockIdx.x] = cs;
    }
}

// ---------------- per-(b,k) compaction: 8 warps, 2-pass deterministic ----------------
__global__ void compact_kernel() {
    __shared__ int   scnt[8];
    __shared__ float smass[8];
    __shared__ int   soff[8];
    int bk = blockIdx.x;
    int b = bk >> 3, k = bk & 7;
    int tid = threadIdx.x;
    int warp = tid >> 5, lane = tid & 31;

    int cnt = 0; float mass = 0.f;
    int base0 = warp * 512;
    for (int i = 0; i < 16; i++) {
        int n = base0 + i * 32 + lane;
        unsigned short e = g_route_e[b * NN + n];
        float2 wv = g_route_w[b * NN + n];
        bool m0 = (e & 0xff) == k;
        bool m1 = (e >> 8)   == k;
        bool hit = m0 || m1;
        unsigned bal = __ballot_sync(0xffffffffu, hit);
        cnt += __popc(bal);
        if (hit) mass += m0 ? wv.x : wv.y;
    }
#pragma unroll
    for (int off = 16; off; off >>= 1) mass += __shfl_xor_sync(0xffffffffu, mass, off);
    if (lane == 0) { scnt[warp] = cnt; smass[warp] = mass; }
    __syncthreads();
    if (tid == 0) {
        int run = 0; float msum = 0.f;
#pragma unroll
        for (int w = 0; w < 8; w++) { soff[w] = run; run += scnt[w]; msum += smass[w]; }
        g_cnt[bk] = run;
        g_mass[bk] = msum;
    }
    __syncthreads();

    int pos = soff[warp];
    for (int i = 0; i < 16; i++) {
        int n = base0 + i * 32 + lane;
        unsigned short e = g_route_e[b * NN + n];
        float2 wv = g_route_w[b * NN + n];
        bool m0 = (e & 0xff) == k;
        bool m1 = (e >> 8)   == k;
        bool hit = m0 || m1;
        unsigned bal = __ballot_sync(0xffffffffu, hit);
        if (hit) {
            int p = pos + __popc(bal & ((1u << lane) - 1u));
            g_list[bk][p] = (unsigned short)n;
            g_wt[bk][p]   = m0 ? wv.x : wv.y;
        }
        pos += __popc(bal);
    }
}

// ================= expert layer-1: persistent, mma.sync bf16x2, pipelined LDSM =================
#define ROWB 528
#define OFF_BH 0
#define OFF_BL (128 * ROWB)
#define BL_DELTA (OFF_BL - OFF_BH)
#define OFF_A0 (2 * 128 * ROWB)
#define OFF_A1 (OFF_A0 + 64 * ROWB)
#define OFF_WT (OFF_A1 + 64 * ROWB)
#define OFF_B1 (OFF_WT + 512)
#define OFF_RED (OFF_B1 + 512)
#define OFF_ITEM (OFF_RED + 512)
#define SM_TOTAL (OFF_ITEM + 16)

__device__ __forceinline__ uint32_t smem_u32(const void* p) {
    uint32_t a;
    asm("{ .reg .u64 t; cvta.to.shared.u64 t, %1; cvt.u32.u64 %0, t; }" : "=r"(a) : "l"(p));
    return a;
}
__device__ __forceinline__ uint32_t pack_bf2(float a, float b) {
    uint32_t r;
    asm("cvt.rn.bf16x2.f32 %0, %1, %2;" : "=r"(r) : "f"(b), "f"(a));
    return r;
}
__device__ __forceinline__ void split2(float x, float y, uint32_t& hi, uint32_t& lo) {
    float hx = __bfloat162float(__float2bfloat16(x));
    float hy = __bfloat162float(__float2bfloat16(y));
    hi = pack_bf2(x, y);
    lo = pack_bf2(x - hx, y - hy);
}
__device__ __forceinline__ void mma16816(float* c, const uint32_t* a, const uint32_t* b) {
    asm volatile("mma.sync.aligned.m16n8k16.row.col.f32.bf16.bf16.f32 "
        "{%0,%1,%2,%3}, {%4,%5,%6,%7}, {%8,%9}, {%0,%1,%2,%3};"
        : "+f"(c[0]), "+f"(c[1]), "+f"(c[2]), "+f"(c[3])
        : "r"(a[0]), "r"(a[1]), "r"(a[2]), "r"(a[3]), "r"(b[0]), "r"(b[1]));
}
#define LDSM4(r, addr) \
    asm volatile("ldmatrix.sync.aligned.m8n8.x4.shared.b16 {%0,%1,%2,%3}, [%4];" \
        : "=r"((r)[0]), "=r"((r)[1]), "=r"((r)[2]), "=r"((r)[3]) : "r"(addr))

__global__ void __launch_bounds__(512, 1)
expert_kernel(const float* __restrict__ tokens,
              const float* __restrict__ W1,
              const float* __restrict__ b1) {
    extern __shared__ char sm[];
    uint32_t smemu = smem_u32(sm);
    int tid = threadIdx.x;
    int warp = tid >> 5, lane = tid & 31;
    int warpN = warp & 7, warpM = warp >> 3;

    // per-thread invariant LDSM offsets
    uint32_t aA_row = (uint32_t)((warpM * 32 + (lane & 15)) * ROWB + ((lane & 16) ? 16 : 0));
    uint32_t aB_off = (uint32_t)OFF_BH
        + (uint32_t)((warpN * 16 + (lane & 7) + ((lane & 16) ? 8 : 0)) * ROWB
                     + ((lane & 8) ? 16 : 0));
    int prow = tid >> 3, pseg = tid & 7;

    for (;;) {
        // ---- fetch next work item ----
        if (tid == 0) *(int*)(sm + OFF_ITEM) = atomicAdd(&g_item, 1);
        __syncthreads();                         // also: prev item's readers done
        int item = *(int*)(sm + OFF_ITEM);
        if (item >= NITEMS) break;

        int b = item >> 4, k = (item >> 1) & 7, half = item & 1;
        int bk = b * KK + k;
        int cnt = g_cnt[bk];
        int ntiles = (cnt + 63) >> 6;

        // ---- stage W1 half as bf16 hi/lo ----
        {
            int row = tid >> 2, q = tid & 3;
            const float4* src = (const float4*)(W1 + (size_t)k * CC * CC
                                                + (size_t)(half * 128 + row) * CC);
            char* rh = sm + OFF_BH + row * ROWB;
            char* rl = sm + OFF_BL + row * ROWB;
#pragma unroll 4
            for (int j = 0; j < 16; j++) {
                int cc = j * 4 + q;
                float4 v = src[cc];
                uint32_t h0, l0, h1, l1;
                split2(v.x, v.y, h0, l0);
                split2(v.z, v.w, h1, l1);
                *(uint2*)(rh + cc * 8) = make_uint2(h0, h1);
                *(uint2*)(rl + cc * 8) = make_uint2(l0, l1);
            }
            if (tid < 128) ((float*)(sm + OFF_B1))[tid] = b1[k * CC + half * 128 + tid];
        }

        // ---- prologue: stage tile 0 into buf 0 ----
        {
            bool valid = prow < cnt;
            int n = valid ? (int)g_list[bk][prow] : 0;
            if (pseg == 0) ((float*)(sm + OFF_WT))[prow] = valid ? g_wt[bk][prow] : 0.f;
            const float4* src = (const float4*)(tokens + ((size_t)b * NN + n) * CC);
            char* ra = sm + OFF_A0 + prow * ROWB;
#pragma unroll
            for (int j = 0; j < 8; j++) {
                float4 v = src[j * 8 + pseg];
                *(uint2*)(ra + (j * 8 + pseg) * 8) = make_uint2(pack_bf2(v.x, v.y), pack_bf2(v.z, v.w));
            }
        }
        __syncthreads();

        float acc[2][2][4];
#pragma unroll
        for (int mt = 0; mt < 2; mt++)
#pragma unroll
            for (int nt = 0; nt < 2; nt++)
#pragma unroll
                for (int j = 0; j < 4; j++) acc[mt][nt][j] = 0.f;
        float colsum[2][2] = {{0.f, 0.f}, {0.f, 0.f}};

        const float* sb1 = (const float*)(sm + OFF_B1);
        uint32_t aB_base = smemu + aB_off;

        for (int t = 0; t < ntiles; t++) {
            int cur = t & 1;
            uint32_t aA_base = smemu + (cur ? OFF_A1 : OFF_A0) + aA_row;

            // prefetch next tile (LDG + convert, held in regs)
            uint2 pu[8];
            float pwt = 0.f;
            bool havenext = (t + 1 < ntiles);
            if (havenext) {
                int slot = (t + 1) * 64 + prow;
                bool valid = slot < cnt;
                int n = valid ? (int)g_list[bk][slot] : 0;
                if (pseg == 0) pwt = valid ? g_wt[bk][slot] : 0.f;
                const float4* src = (const float4*)(tokens + ((size_t)b * NN + n) * CC);
#pragma unroll
                for (int j = 0; j < 8; j++) {
                    float4 v = src[j * 8 + pseg];
                    pu[j] = make_uint2(pack_bf2(v.x, v.y), pack_bf2(v.z, v.w));
                }
            }

            // ---- K loop: software-pipelined (frags for k+1 load before MMAs of k) ----
            uint32_t fa[2][8], fb[2][8];
            LDSM4(fa[0] + 0, aA_base);
            LDSM4(fa[0] + 4, aA_base + 16 * ROWB);
            LDSM4(fb[0] + 0, aB_base);
            LDSM4(fb[0] + 4, aB_base + BL_DELTA);
#pragma unroll
            for (int ks = 0; ks < 16; ks++) {
                int c = ks & 1, nx = 1 - c;
                if (ks < 15) {
                    uint32_t kb = (uint32_t)((ks + 1) * 32);
                    LDSM4(fa[nx] + 0, aA_base + kb);
                    LDSM4(fa[nx] + 4, aA_base + 16 * ROWB + kb);
                    LDSM4(fb[nx] + 0, aB_base + kb);
                    LDSM4(fb[nx] + 4, aB_base + BL_DELTA + kb);
                }
                mma16816(acc[0][0], fa[c] + 0, fb[c] + 0);
                mma16816(acc[0][1], fa[c] + 0, fb[c] + 2);
                mma16816(acc[1][0], fa[c] + 4, fb[c] + 0);
                mma16816(acc[1][1], fa[c] + 4, fb[c] + 2);
                mma16816(acc[0][0], fa[c] + 0, fb[c] + 4);
                mma16816(acc[0][1], fa[c] + 0, fb[c] + 6);
                mma16816(acc[1][0], fa[c] + 4, fb[c] + 4);
                mma16816(acc[1][1], fa[c] + 4, fb[c] + 6);
            }

            // ---- fused epilogue ----
            {
                const float* swt = (const float*)(sm + OFF_WT) + cur * 64;
#pragma unroll
                for (int mt = 0; mt < 2; mt++) {
                    int r0 = warpM * 32 + mt * 16 + (lane >> 2);
                    float w0 = swt[r0], w1 = swt[r0 + 8];
#pragma unroll
                    for (int nt = 0; nt < 2; nt++) {
                        int c0 = warpN * 16 + nt * 8 + (lane & 3) * 2;
                        float bb0 = sb1[c0], bb1 = sb1[c0 + 1];
                        colsum[nt][0] += w0 * fmaxf(acc[mt][nt][0] + bb0, 0.f)
                                       + w1 * fmaxf(acc[mt][nt][2] + bb0, 0.f);
                        colsum[nt][1] += w0 * fmaxf(acc[mt][nt][1] + bb1, 0.f)
                                       + w1 * fmaxf(acc[mt][nt][3] + bb1, 0.f);
#pragma unroll
                        for (int j = 0; j < 4; j++) acc[mt][nt][j] = 0.f;
                    }
                }
            }

            // ---- commit prefetched tile into the other buffer ----
            if (havenext) {
                char* ra = sm + (cur ? OFF_A0 : OFF_A1) + prow * ROWB;
#pragma unroll
                for (int j = 0; j < 8; j++)
                    *(uint2*)(ra + (j * 8 + pseg) * 8) = pu[j];
                if (pseg == 0)
                    ((float*)(sm + OFF_WT))[(1 - cur) * 64 + prow] = pwt;
            }
            __syncthreads();
        }

        // ---- reduce over lane row-groups, then across warpM, write ----
#pragma unroll
        for (int nt = 0; nt < 2; nt++)
#pragma unroll
            for (int j = 0; j < 2; j++) {
#pragma unroll
                for (int off = 4; off <= 16; off <<= 1)
                    colsum[nt][j] += __shfl_xor_sync(0xffffffffu, colsum[nt][j], off);
            }
        float* sred = (float*)(sm + OFF_RED);
        if (warpM == 1 && lane < 4) {
#pragma unroll
            for (int nt = 0; nt < 2; nt++) {
                int c = warpN * 16 + nt * 8 + lane * 2;
                sred[c]     = colsum[nt][0];
                sred[c + 1] = colsum[nt][1];
            }
        }
        __syncthreads();
        if (warpM == 0 && lane < 4) {
#pragma unroll
            for (int nt = 0; nt < 2; nt++) {
                int c = warpN * 16 + nt * 8 + lane * 2;
                g_hacc[bk * CC + half * 128 + c]     = colsum[nt][0] + sred[c];
                g_hacc[bk * CC + half * 128 + c + 1] = colsum[nt][1] + sred[c + 1];
            }
        }
    }
}

// ---------------- layer-2 + normalize -> centers (split-K, 512 thr) ----------------
__global__ void out_kernel(const float* __restrict__ W2,
                           const float* __restrict__ b2,
                           float* __restrict__ out) {
    __shared__ float sh[CC];
    __shared__ float spar[256];
    int bk = blockIdx.x;
    int k = bk & 7;
    int tid = threadIdx.x;
    int c = tid & 255, kh = tid >> 8;
    if (kh == 0) sh[c] = g_hacc[bk * CC + c];
    __syncthreads();
    const float4* w4 = (const float4*)(W2 + ((size_t)k * CC + c) * CC) + kh * 32;
    const float* shh = sh + kh * 128;
    float p0 = 0.f, p1 = 0.f, p2 = 0.f, p3 = 0.f;
#pragma unroll 8
    for (int j = 0; j < 32; j++) {
        float4 w = w4[j];
        p0 += shh[4*j]   * w.x;
        p1 += shh[4*j+1] * w.y;
        p2 += shh[4*j+2] * w.z;
        p3 += shh[4*j+3] * w.w;
    }
    float s = (p0 + p1) + (p2 + p3);
    if (kh == 1) spar[c] = s;
    __syncthreads();
    if (kh == 0) {
        s += spar[c];
        float mass = g_mass[bk];
        s += mass * b2[k * CC + c];
        s /= fmaxf(mass, EPSF);
        out[bk * CC + c] = s;
    }
}

// ---------------- scalars: lb_loss (from g_cnt) + routing_confidence ----------------
__global__ void fin_kernel(float* __restrict__ out) {
    __shared__ float sred[256];
    int tid = threadIdx.x;
    float s = 0.f;
    for (int i = tid; i < GATE_BLOCKS; i += 256) s += g_conf[i];
    sred[tid] = s;
    __syncthreads();
    for (int off = 128; off; off >>= 1) {
        if (tid < off) sred[tid] += sred[tid + off];
        __syncthreads();
    }
    if (tid == 0) {
        float rc = sred[0] / (float)NTOK;
        float u[KK]; float mean = 0.f;
#pragma unroll
        for (int k = 0; k < KK; k++) {
            int c = 0;
#pragma unroll
            for (int b = 0; b < BB; b++) c += g_cnt[b * KK + k];
            u[k] = (float)c / (float)NTOK;
            mean += u[k];
        }
        mean /= (float)KK;
        float var = 0.f;
#pragma unroll
        for (int k = 0; k < KK; k++) { float d = u[k] - mean; var += d * d; }
        var /= (float)KK;
        float den = mean + EPSF;
        out[BB * KK * CC]     = var / (den * den);
        out[BB * KK * CC + 1] = rc;
    }
}

// ---------------- launch ----------------
extern "C" void kernel_launch(void* const* d_in, const int* in_sizes, int n_in,
                              void* d_out, int out_size) {
    const float* tokens = (const float*)d_in[0];
    const float* geno   = (const float*)d_in[1];
    const float* Wg     = (const float*)d_in[2];
    const float* bg     = (const float*)d_in[3];
    const float* Wgg    = (const float*)d_in[4];
    const float* bgg    = (const float*)d_in[5];
    const float* W1     = (const float*)d_in[6];
    const float* b1     = (const float*)d_in[7];
    const float* W2     = (const float*)d_in[8];
    const float* b2     = (const float*)d_in[9];
    float* out = (float*)d_out;

    cudaFuncSetAttribute(expert_kernel, cudaFuncAttributeMaxDynamicSharedMemorySize, SM_TOTAL);

    geno_kernel<<<1, 128>>>(geno, Wgg, bgg);
    gate_kernel<<<GATE_BLOCKS, 256>>>(tokens, Wg, bg);
    compact_kernel<<<BB * KK, 256>>>();
    expert_kernel<<<148, 512, SM_TOTAL>>>(tokens, W1, b1);
    out_kernel<<<BB * KK, 512>>>(W2, b2, out);
    if (out_size >= BB * KK * CC + 2) fin_kernel<<<1, 256>>>(out);
}

// round 8
// speedup vs baseline: 10.2123x; 1.1926x over previous
#include <cuda_runtime.h>
#include <cuda_bf16.h>
#include <math.h>
#include <stdint.h>

#define BB 16
#define NN 4096
#define CC 256
#define KK 8
#define EPSF 1e-6f
#define RATIOF 0.1f
#define NTOK (BB*NN)          // 65536
#define GATE_BLOCKS (NTOK/16) // 4096
#define NITEMS (BB*KK)        // 128 expert work items (b,k)

// ---------------- scratch globals ----------------
__device__ float          g_geno[BB*KK];
__device__ unsigned short g_route_e[NTOK];
__device__ float2         g_route_w[NTOK];
__device__ float          g_conf[GATE_BLOCKS];
__device__ float          g_hacc[BB*KK*CC];
__device__ float          g_mass[BB*KK];
__device__ unsigned short g_list[BB*KK][NN];
__device__ float          g_wt[BB*KK][NN];
__device__ int            g_cnt[BB*KK];
__device__ int            g_item;
__device__ __nv_bfloat16  g_tokbf[(size_t)NTOK*CC];   // bf16 token copy (written by gate)

// ---------------- helpers ----------------
__device__ __forceinline__ uint32_t smem_u32(const void* p) {
    uint32_t a;
    asm("{ .reg .u64 t; cvta.to.shared.u64 t, %1; cvt.u32.u64 %0, t; }" : "=r"(a) : "l"(p));
    return a;
}
__device__ __forceinline__ uint32_t pack_bf2(float a, float b) {
    uint32_t r;
    asm("cvt.rn.bf16x2.f32 %0, %1, %2;" : "=r"(r) : "f"(b), "f"(a));
    return r;
}
__device__ __forceinline__ void mma16816(float* c, const uint32_t* a, const uint32_t* b) {
    asm volatile("mma.sync.aligned.m16n8k16.row.col.f32.bf16.bf16.f32 "
        "{%0,%1,%2,%3}, {%4,%5,%6,%7}, {%8,%9}, {%0,%1,%2,%3};"
        : "+f"(c[0]), "+f"(c[1]), "+f"(c[2]), "+f"(c[3])
        : "r"(a[0]), "r"(a[1]), "r"(a[2]), "r"(a[3]), "r"(b[0]), "r"(b[1]));
}
#define LDSM4(r, addr) \
    asm volatile("ldmatrix.sync.aligned.m8n8.x4.shared.b16 {%0,%1,%2,%3}, [%4];" \
        : "=r"((r)[0]), "=r"((r)[1]), "=r"((r)[2]), "=r"((r)[3]) : "r"(addr))
#define CP_ASYNC16(dst, src) \
    asm volatile("cp.async.cg.shared.global [%0], [%1], 16;" :: "r"(dst), "l"(src))
#define CP_COMMIT() asm volatile("cp.async.commit_group;" ::: "memory")
#define CP_WAIT0()  asm volatile("cp.async.wait_group 0;" ::: "memory")

// ---------------- geno term + work-counter reset ----------------
__global__ void geno_kernel(const float* __restrict__ geno_vec,
                            const float* __restrict__ Wgg,
                            const float* __restrict__ bgg) {
    int t = threadIdx.x;            // 128 = B*K
    int b = t / KK, k = t % KK;
    const float* g = geno_vec + b * CC;
    const float* w = Wgg + k * CC;
    float s = 0.f;
#pragma unroll 8
    for (int i = 0; i < CC; i++) s += g[i] * w[i];
    g_geno[t] = RATIOF * (s + bgg[k]);
    if (t == 0) g_item = 0;
}

// ---------------- gate: logits/top-2/softmax + bf16 token copy ----------------
__global__ void gate_kernel(const float* __restrict__ tokens,
                            const float* __restrict__ Wg,
                            const float* __restrict__ bg) {
    __shared__ float4 sWg[KK * 64];
    __shared__ float  sconf[16];
    int tid = threadIdx.x;
    for (int i = tid; i < KK * 64; i += 256) sWg[i] = ((const float4*)Wg)[i];
    __syncthreads();

    int warp = tid >> 5, lane = tid & 31;
    int t0 = blockIdx.x * 16 + warp * 2;
    int b = t0 >> 12;

    float acc[2][KK];
#pragma unroll
    for (int u = 0; u < 2; u++)
#pragma unroll
        for (int k = 0; k < KK; k++) acc[u][k] = 0.f;

    uint2* bf0 = (uint2*)(g_tokbf + (size_t)t0 * CC);
    uint2* bf1 = (uint2*)(g_tokbf + (size_t)(t0 + 1) * CC);
#pragma unroll
    for (int i = 0; i < 2; i++) {
        float4 tv0 = ((const float4*)(tokens + (size_t)t0 * CC))[i * 32 + lane];
        float4 tv1 = ((const float4*)(tokens + (size_t)(t0 + 1) * CC))[i * 32 + lane];
        bf0[i * 32 + lane] = make_uint2(pack_bf2(tv0.x, tv0.y), pack_bf2(tv0.z, tv0.w));
        bf1[i * 32 + lane] = make_uint2(pack_bf2(tv1.x, tv1.y), pack_bf2(tv1.z, tv1.w));
#pragma unroll
        for (int k = 0; k < KK; k++) {
            float4 w = sWg[k * 64 + i * 32 + lane];
            acc[0][k] += tv0.x * w.x + tv0.y * w.y + tv0.z * w.z + tv0.w * w.w;
            acc[1][k] += tv1.x * w.x + tv1.y * w.y + tv1.z * w.z + tv1.w * w.w;
        }
    }
#pragma unroll
    for (int k = 0; k < KK; k++) {
#pragma unroll
        for (int off = 16; off; off >>= 1) {
            acc[0][k] += __shfl_xor_sync(0xffffffffu, acc[0][k], off);
            acc[1][k] += __shfl_xor_sync(0xffffffffu, acc[1][k], off);
        }
    }
    if (lane < 2) {
        int t = t0 + lane;
        float lg[KK];
#pragma unroll
        for (int k = 0; k < KK; k++) {
            float a = __shfl_sync(0x3u, acc[0][k], 0) * (lane == 0 ? 1.f : 0.f)
                    + __shfl_sync(0x3u, acc[1][k], 0) * (lane == 1 ? 1.f : 0.f);
            lg[k] = a + bg[k] + g_geno[b * KK + k];
        }
        int i0 = 0; float v0 = lg[0];
#pragma unroll
        for (int k = 1; k < KK; k++) if (lg[k] > v0) { v0 = lg[k]; i0 = k; }
        float v1 = -1e30f; int i1 = 0;
#pragma unroll
        for (int k = 0; k < KK; k++)
            if (k != i0 && lg[k] > v1) { v1 = lg[k]; i1 = k; }
        float e  = expf(v1 - v0);
        float w0 = 1.f / (1.f + e);
        float w1 = e / (1.f + e);
        w0 = fmaxf(w0, EPSF); w1 = fmaxf(w1, EPSF);
        float s = w0 + w1; w0 /= s; w1 /= s;
        g_route_e[t] = (unsigned short)(i0 | (i1 << 8));
        g_route_w[t] = make_float2(w0, w1);
        sconf[warp * 2 + lane] = v0 - v1;
    }
    __syncthreads();
    if (tid == 0) {
        float cs = 0.f;
#pragma unroll
        for (int w = 0; w < 16; w++) cs += sconf[w];
        g_conf[blockIdx.x] = cs;
    }
}

// ---------------- per-(b,k) compaction ----------------
__global__ void compact_kernel() {
    __shared__ int   scnt[8];
    __shared__ float smass[8];
    __shared__ int   soff[8];
    int bk = blockIdx.x;
    int b = bk >> 3, k = bk & 7;
    int tid = threadIdx.x;
    int warp = tid >> 5, lane = tid & 31;

    int cnt = 0; float mass = 0.f;
    int base0 = warp * 512;
    for (int i = 0; i < 16; i++) {
        int n = base0 + i * 32 + lane;
        unsigned short e = g_route_e[b * NN + n];
        float2 wv = g_route_w[b * NN + n];
        bool m0 = (e & 0xff) == k;
        bool m1 = (e >> 8)   == k;
        bool hit = m0 || m1;
        unsigned bal = __ballot_sync(0xffffffffu, hit);
        cnt += __popc(bal);
        if (hit) mass += m0 ? wv.x : wv.y;
    }
#pragma unroll
    for (int off = 16; off; off >>= 1) mass += __shfl_xor_sync(0xffffffffu, mass, off);
    if (lane == 0) { scnt[warp] = cnt; smass[warp] = mass; }
    __syncthreads();
    if (tid == 0) {
        int run = 0; float msum = 0.f;
#pragma unroll
        for (int w = 0; w < 8; w++) { soff[w] = run; run += scnt[w]; msum += smass[w]; }
        g_cnt[bk] = run;
        g_mass[bk] = msum;
    }
    __syncthreads();

    int pos = soff[warp];
    for (int i = 0; i < 16; i++) {
        int n = base0 + i * 32 + lane;
        unsigned short e = g_route_e[b * NN + n];
        float2 wv = g_route_w[b * NN + n];
        bool m0 = (e & 0xff) == k;
        bool m1 = (e >> 8)   == k;
        bool hit = m0 || m1;
        unsigned bal = __ballot_sync(0xffffffffu, hit);
        if (hit) {
            int p = pos + __popc(bal & ((1u << lane) - 1u));
            g_list[bk][p] = (unsigned short)n;
            g_wt[bk][p]   = m0 ? wv.x : wv.y;
        }
        pos += __popc(bal);
    }
}

// ================= expert layer-1: persistent, pure bf16, 32x32 warp tiles =================
// item = (b,k). Block tile: M=64 (double-buffered, cp.async from g_tokbf) x N=256.
// 512 threads = 16 warps: warpN = warp&7 (32 cols), warpM = warp>>3 (32 rows).
#define ROWB 528
#define OFF_B   0                                   // 256 rows x 528 B (bf16 W1 rows)
#define OFF_A0  (256 * ROWB)                        // 135168
#define OFF_A1  (OFF_A0 + 64 * ROWB)                // 168960
#define OFF_WT  (OFF_A1 + 64 * ROWB)                // 202752 : 2 x 64 floats
#define OFF_B1  (OFF_WT + 512)                      // 256 floats
#define OFF_RED (OFF_B1 + 1024)                     // 256 floats
#define OFF_ITEM (OFF_RED + 1024)
#define SM_TOTAL (OFF_ITEM + 16)

__global__ void __launch_bounds__(512, 1)
expert_kernel(const float* __restrict__ W1,
              const float* __restrict__ b1) {
    extern __shared__ char sm[];
    uint32_t smemu = smem_u32(sm);
    int tid = threadIdx.x;
    int warp = tid >> 5, lane = tid & 31;
    int warpN = warp & 7, warpM = warp >> 3;

    // invariant LDSM offsets
    uint32_t aA_off = (uint32_t)((warpM * 32 + (lane & 15)) * ROWB + ((lane & 16) ? 16 : 0));
    uint32_t aB_base = smemu + OFF_B
        + (uint32_t)((warpN * 32 + (lane & 7) + ((lane & 16) ? 8 : 0)) * ROWB
                     + ((lane & 8) ? 16 : 0));
    // cp.async gather geometry: 64 rows x 8 threads/row x 4 chunks of 16B
    int grow = tid >> 3, gseg = tid & 7;

    for (;;) {
        if (tid == 0) *(int*)(sm + OFF_ITEM) = atomicAdd(&g_item, 1);
        __syncthreads();
        int item = *(int*)(sm + OFF_ITEM);
        if (item >= NITEMS) break;

        int b = item >> 3, k = item & 7;
        int bk = item;
        int cnt = g_cnt[bk];
        int ntiles = (cnt + 63) >> 6;

        // ---- stage W1[k] (256x256) as bf16 rows ----
        {
            int row = tid >> 1, hf = tid & 1;       // 256 rows x 2 half-rows
            const float4* src = (const float4*)(W1 + (size_t)k * CC * CC
                                                + (size_t)row * CC + hf * 128);
            char* rb = sm + OFF_B + row * ROWB + hf * 256;
#pragma unroll 8
            for (int j = 0; j < 32; j++) {
                float4 v = src[j];
                *(uint2*)(rb + j * 8) = make_uint2(pack_bf2(v.x, v.y), pack_bf2(v.z, v.w));
            }
            if (tid < 256) ((float*)(sm + OFF_B1))[tid] = b1[k * CC + tid];
        }

        // ---- prologue: cp.async tile 0 -> buf0 ----
        if (ntiles > 0) {
            int slot = grow;
            int n = (int)g_list[bk][slot < cnt ? slot : cnt - 1];
            const char* src = (const char*)(g_tokbf + ((size_t)b * NN + n) * CC) + gseg * 64;
            uint32_t dst = smemu + OFF_A0 + grow * ROWB + gseg * 64;
#pragma unroll
            for (int j = 0; j < 4; j++) CP_ASYNC16(dst + j * 16, src + j * 16);
            CP_COMMIT();
            if (tid < 64)
                ((float*)(sm + OFF_WT))[tid] = (tid < cnt) ? g_wt[bk][tid] : 0.f;
        }
        CP_WAIT0();
        __syncthreads();

        float acc[2][4][4];
#pragma unroll
        for (int mt = 0; mt < 2; mt++)
#pragma unroll
            for (int j = 0; j < 4; j++)
#pragma unroll
                for (int q = 0; q < 4; q++) acc[mt][j][q] = 0.f;
        float colsum[4][2];
#pragma unroll
        for (int j = 0; j < 4; j++) colsum[j][0] = colsum[j][1] = 0.f;

        const float* sb1 = (const float*)(sm + OFF_B1);

        for (int t = 0; t < ntiles; t++) {
            int cur = t & 1;

            // prefetch next tile via cp.async into other buffer
            if (t + 1 < ntiles) {
                int slot = (t + 1) * 64 + grow;
                int n = (int)g_list[bk][slot < cnt ? slot : cnt - 1];
                const char* src = (const char*)(g_tokbf + ((size_t)b * NN + n) * CC) + gseg * 64;
                uint32_t dst = smemu + (cur ? OFF_A0 : OFF_A1) + grow * ROWB + gseg * 64;
#pragma unroll
                for (int j = 0; j < 4; j++) CP_ASYNC16(dst + j * 16, src + j * 16);
                CP_COMMIT();
                if (tid < 64) {
                    int s2 = (t + 1) * 64 + tid;
                    ((float*)(sm + OFF_WT))[(1 - cur) * 64 + tid] =
                        (s2 < cnt) ? g_wt[bk][s2] : 0.f;
                }
            }

            // ---- K loop: 16 steps, 4 LDSM + 8 HMMA (all-distinct accumulators) ----
            uint32_t aA_base = smemu + (cur ? OFF_A1 : OFF_A0) + aA_off;
#pragma unroll
            for (int ks = 0; ks < 16; ks++) {
                uint32_t kb = (uint32_t)(ks * 32);
                uint32_t fa0[4], fa1[4], fb0[4], fb1[4];
                LDSM4(fa0, aA_base + kb);
                LDSM4(fa1, aA_base + 16 * ROWB + kb);
                LDSM4(fb0, aB_base + kb);
                LDSM4(fb1, aB_base + 16 * ROWB + kb);
                mma16816(acc[0][0], fa0, fb0 + 0);
                mma16816(acc[0][1], fa0, fb0 + 2);
                mma16816(acc[0][2], fa0, fb1 + 0);
                mma16816(acc[0][3], fa0, fb1 + 2);
                mma16816(acc[1][0], fa1, fb0 + 0);
                mma16816(acc[1][1], fa1, fb0 + 2);
                mma16816(acc[1][2], fa1, fb1 + 0);
                mma16816(acc[1][3], fa1, fb1 + 2);
            }

            // ---- fused epilogue ----
            {
                const float* swt = (const float*)(sm + OFF_WT) + cur * 64;
#pragma unroll
                for (int mt = 0; mt < 2; mt++) {
                    int r0 = warpM * 32 + mt * 16 + (lane >> 2);
                    float w0 = swt[r0], w1 = swt[r0 + 8];
#pragma unroll
                    for (int j = 0; j < 4; j++) {
                        int c0 = warpN * 32 + j * 8 + (lane & 3) * 2;
                        float bb0 = sb1[c0], bb1 = sb1[c0 + 1];
                        colsum[j][0] += w0 * fmaxf(acc[mt][j][0] + bb0, 0.f)
                                      + w1 * fmaxf(acc[mt][j][2] + bb0, 0.f);
                        colsum[j][1] += w0 * fmaxf(acc[mt][j][1] + bb1, 0.f)
                                      + w1 * fmaxf(acc[mt][j][3] + bb1, 0.f);
#pragma unroll
                        for (int q = 0; q < 4; q++) acc[mt][j][q] = 0.f;
                    }
                }
            }

            CP_WAIT0();
            __syncthreads();
        }

        // ---- reduce row-groups (shfl), then across warpM (smem), write ----
#pragma unroll
        for (int j = 0; j < 4; j++)
#pragma unroll
            for (int q = 0; q < 2; q++) {
#pragma unroll
                for (int off = 4; off <= 16; off <<= 1)
                    colsum[j][q] += __shfl_xor_sync(0xffffffffu, colsum[j][q], off);
            }
        float* sred = (float*)(sm + OFF_RED);
        if (warpM == 1 && lane < 4) {
#pragma unroll
            for (int j = 0; j < 4; j++) {
                int c = warpN * 32 + j * 8 + lane * 2;
                sred[c]     = colsum[j][0];
                sred[c + 1] = colsum[j][1];
            }
        }
        __syncthreads();
        if (warpM == 0 && lane < 4) {
#pragma unroll
            for (int j = 0; j < 4; j++) {
                int c = warpN * 32 + j * 8 + lane * 2;
                g_hacc[bk * CC + c]     = colsum[j][0] + sred[c];
                g_hacc[bk * CC + c + 1] = colsum[j][1] + sred[c + 1];
            }
        }
#pragma unroll
        for (int j = 0; j < 4; j++) colsum[j][0] = colsum[j][1] = 0.f;
    }
}

// ---------------- layer-2 + normalize -> centers (split-K, 512 thr) ----------------
__global__ void out_kernel(const float* __restrict__ W2,
                           const float* __restrict__ b2,
                           float* __restrict__ out) {
    __shared__ float sh[CC];
    __shared__ float spar[256];
    int bk = blockIdx.x;
    int k = bk & 7;
    int tid = threadIdx.x;
    int c = tid & 255, kh = tid >> 8;
    if (kh == 0) sh[c] = g_hacc[bk * CC + c];
    __syncthreads();
    const float4* w4 = (const float4*)(W2 + ((size_t)k * CC + c) * CC) + kh * 32;
    const float* shh = sh + kh * 128;
    float p0 = 0.f, p1 = 0.f, p2 = 0.f, p3 = 0.f;
#pragma unroll 8
    for (int j = 0; j < 32; j++) {
        float4 w = w4[j];
        p0 += shh[4*j]   * w.x;
        p1 += shh[4*j+1] * w.y;
        p2 += shh[4*j+2] * w.z;
        p3 += shh[4*j+3] * w.w;
    }
    float s = (p0 + p1) + (p2 + p3);
    if (kh == 1) spar[c] = s;
    __syncthreads();
    if (kh == 0) {
        s += spar[c];
        float mass = g_mass[bk];
        s += mass * b2[k * CC + c];
        s /= fmaxf(mass, EPSF);
        out[bk * CC + c] = s;
    }
}

// ---------------- scalars ----------------
__global__ void fin_kernel(float* __restrict__ out) {
    __shared__ float sred[256];
    int tid = threadIdx.x;
    float s = 0.f;
    for (int i = tid; i < GATE_BLOCKS; i += 256) s += g_conf[i];
    sred[tid] = s;
    __syncthreads();
    for (int off = 128; off; off >>= 1) {
        if (tid < off) sred[tid] += sred[tid + off];
        __syncthreads();
    }
    if (tid == 0) {
        float rc = sred[0] / (float)NTOK;
        float u[KK]; float mean = 0.f;
#pragma unroll
        for (int k = 0; k < KK; k++) {
            int c = 0;
#pragma unroll
            for (int b = 0; b < BB; b++) c += g_cnt[b * KK + k];
            u[k] = (float)c / (float)NTOK;
            mean += u[k];
        }
        mean /= (float)KK;
        float var = 0.f;
#pragma unroll
        for (int k = 0; k < KK; k++) { float d = u[k] - mean; var += d * d; }
        var /= (float)KK;
        float den = mean + EPSF;
        out[BB * KK * CC]     = var / (den * den);
        out[BB * KK * CC + 1] = rc;
    }
}

// ---------------- launch ----------------
extern "C" void kernel_launch(void* const* d_in, const int* in_sizes, int n_in,
                              void* d_out, int out_size) {
    const float* tokens = (const float*)d_in[0];
    const float* geno   = (const float*)d_in[1];
    const float* Wg     = (const float*)d_in[2];
    const float* bg     = (const float*)d_in[3];
    const float* Wgg    = (const float*)d_in[4];
    const float* bgg    = (const float*)d_in[5];
    const float* W1     = (const float*)d_in[6];
    const float* b1     = (const float*)d_in[7];
    const float* W2     = (const float*)d_in[8];
    const float* b2     = (const float*)d_in[9];
    float* out = (float*)d_out;

    cudaFuncSetAttribute(expert_kernel, cudaFuncAttributeMaxDynamicSharedMemorySize, SM_TOTAL);

    geno_kernel<<<1, 128>>>(geno, Wgg, bgg);
    gate_kernel<<<GATE_BLOCKS, 256>>>(tokens, Wg, bg);
    compact_kernel<<<BB * KK, 256>>>();
    expert_kernel<<<148, 512, SM_TOTAL>>>(W1, b1);
    out_kernel<<<BB * KK, 512>>>(W2, b2, out);
    if (out_size >= BB * KK * CC + 2) fin_kernel<<<1, 256>>>(out);
}